// round 15
// baseline (speedup 1.0000x reference)
#include <cuda_runtime.h>
#include <cuda_fp16.h>
#include <math.h>

#define CCH 128
#define HIM 480
#define WIM 640
#define HWIM (HIM * WIM)
#define NMAX 100000

// Fused transposed fp16 maps: per pixel 384 halves: [0:128]=fm, [128:256]=gx, [256:384]=gy
__device__ __align__(16) __half g_maps[(size_t)HWIM * 384];
// fp16 copy of feature_ref [N][128]
__device__ __align__(16) __half g_ref[(size_t)NMAX * CCH];

// Reduction accumulators: [0..20] upper-tri Hessian, [21..26] g, [27] sum(e^2)
__device__ double g_acc[28];
__device__ double g_H[21];
__device__ double g_g[6];
__device__ float g_R[9], g_t[3];    // accepted
__device__ float g_Rc[9], g_tc[3];  // candidate (target of the next pass)
__device__ float g_lam, g_lr;
__device__ double g_prev_cost;
__device__ unsigned g_counter = 0;

__device__ __forceinline__ int triidx(int i, int j) {  // i <= j
    return i * (13 - i) / 2 + (j - i);
}

__device__ __forceinline__ float2 cvt2(unsigned v) {
    __half2 h = *reinterpret_cast<const __half2*>(&v);
    return __half22float2(h);
}

// fp32 LM solve, run by ONE thread (last block's tail). Builds next candidate.
__device__ __noinline__ void do_solve(int iter, int N) {
    double cost = 0.5 * g_acc[27] / (double)N;
    bool accept;
    if (iter == 0) {
        g_prev_cost = cost;
        accept = true;
    } else {
        bool worse = (cost > g_prev_cost);
        float lam = g_lam * (worse ? 10.0f : 0.1f);
        g_lam = fminf(fmaxf(lam, 1e-6f), 1e4f);
        if (worse) {
            g_lr = fminf(fmaxf(0.1f * g_lr, 1e-3f), 1.0f);
        } else {
            g_lr = 0.1f;
        }
        accept = !worse;
        if (accept) g_prev_cost = cost;
    }
    if (accept) {
        for (int i = 0; i < 21; i++) g_H[i] = g_acc[i];
        for (int i = 0; i < 6; i++) g_g[i] = g_acc[21 + i];
        for (int i = 0; i < 9; i++) g_R[i] = g_Rc[i];
        for (int i = 0; i < 3; i++) g_t[i] = g_tc[i];
    }

    float M[6][7];
    float lam = g_lam;
    for (int i = 0; i < 6; i++) {
        for (int j = i; j < 6; j++) {
            float h = (float)g_H[triidx(i, j)];
            M[i][j] = h;
            M[j][i] = h;
        }
    }
    for (int i = 0; i < 6; i++) {
        float hd = (float)g_H[triidx(i, i)];
        M[i][i] = hd + (hd + 1e-9f) * lam;
        M[i][6] = (float)g_g[i];
    }

    for (int k = 0; k < 6; k++) {
        int p = k;
        float mx = fabsf(M[k][k]);
        for (int r = k + 1; r < 6; r++) {
            float a = fabsf(M[r][k]);
            if (a > mx) { mx = a; p = r; }
        }
        if (p != k) {
            for (int c = k; c < 7; c++) { float tmp = M[k][c]; M[k][c] = M[p][c]; M[p][c] = tmp; }
        }
        float d = M[k][k];
        for (int r = k + 1; r < 6; r++) {
            float f = M[r][k] / d;
            for (int c = k; c < 7; c++) M[r][c] -= f * M[k][c];
        }
    }
    float x[6];
    for (int i = 5; i >= 0; i--) {
        float s = M[i][6];
        for (int j = i + 1; j < 6; j++) s -= M[i][j] * x[j];
        x[i] = s / M[i][i];
    }

    float lr = g_lr;
    float dt0 = -lr * x[0], dt1 = -lr * x[1], dt2 = -lr * x[2];
    float wx = -lr * x[3], wy = -lr * x[4], wz = -lr * x[5];

    float th = sqrtf(wx * wx + wy * wy + wz * wz);
    float Ac, Bc;
    if (th < 1e-7f) { Ac = 1.0f; Bc = 0.5f; }
    else { Ac = sinf(th) / th; Bc = (1.0f - cosf(th)) / (th * th); }
    float Wm[3][3] = {{0.0f, -wz, wy}, {wz, 0.0f, -wx}, {-wy, wx, 0.0f}};
    float W2[3][3];
    for (int i = 0; i < 3; i++)
        for (int j = 0; j < 3; j++) {
            float s = 0.0f;
            for (int k = 0; k < 3; k++) s += Wm[i][k] * Wm[k][j];
            W2[i][j] = s;
        }
    float dR[3][3];
    for (int i = 0; i < 3; i++)
        for (int j = 0; j < 3; j++)
            dR[i][j] = (i == j ? 1.0f : 0.0f) + Ac * Wm[i][j] + Bc * W2[i][j];

    float Rn[3][3], tn[3];
    for (int i = 0; i < 3; i++) {
        for (int j = 0; j < 3; j++) {
            float s = 0.0f;
            for (int k = 0; k < 3; k++) s += dR[i][k] * g_R[k * 3 + j];
            Rn[i][j] = s;
        }
        float s = 0.0f;
        for (int k = 0; k < 3; k++) s += dR[i][k] * g_t[k];
        tn[i] = s;
    }
    tn[0] += dt0; tn[1] += dt1; tn[2] += dt2;

    for (int i = 0; i < 3; i++)
        for (int j = 0; j < 3; j++)
            g_Rc[i * 3 + j] = Rn[i][j];
    for (int i = 0; i < 3; i++) g_tc[i] = tn[i];

    for (int i = 0; i < 28; i++) g_acc[i] = 0.0;
}

__device__ __noinline__ void do_final(int N, float* __restrict__ out) {
    double cost = 0.5 * g_acc[27] / (double)N;
    bool worse = (cost > g_prev_cost);
    const float* R = worse ? g_R : g_Rc;
    const float* t = worse ? g_t : g_tc;
    for (int i = 0; i < 9; i++) out[i] = R[i];
    for (int i = 0; i < 3; i++) out[9 + i] = t[i];
    for (int i = 0; i < 28; i++) g_acc[i] = 0.0;
}

// Transpose all three (C=128, HW) fp32 maps into fp16 g_maps[pix*384 + z*128 + c].
// z==3 slice instead converts feature_ref fp32 -> fp16 (fused refcvt).
// Block (0,0,0) thread (0,0) also performs global-state init.
__global__ void __launch_bounds__(256) k_transpose(const float* __restrict__ fm,
                                                   const float* __restrict__ gx,
                                                   const float* __restrict__ gy,
                                                   const float* __restrict__ ref,
                                                   int N) {
    if (blockIdx.x == 0 && blockIdx.y == 0 && blockIdx.z == 0 &&
        threadIdx.x == 0 && threadIdx.y == 0) {
        for (int i = 0; i < 9; i++) {
            float v = (i % 4 == 0) ? 1.0f : 0.0f;
            g_R[i] = v; g_Rc[i] = v;
        }
        g_t[0] = 1.0f; g_t[1] = 1.0f; g_t[2] = 0.0f;
        g_tc[0] = 1.0f; g_tc[1] = 1.0f; g_tc[2] = 0.0f;
        g_lam = 0.01f; g_lr = 0.1f;
        g_prev_cost = 0.0;
        for (int i = 0; i < 28; i++) g_acc[i] = 0.0;
        g_counter = 0;
    }

    int z = blockIdx.z;
    if (z == 3) {
        // refcvt: grid-stride over 4-float chunks
        int tid = (blockIdx.y * gridDim.x + blockIdx.x) * 256 + threadIdx.y * 32 + threadIdx.x;
        int nThreads = gridDim.x * gridDim.y * 256;
        int total4 = N * (CCH / 4);
        for (int idx = tid; idx < total4; idx += nThreads) {
            float4 v = *(const float4*)&ref[(size_t)idx * 4];
            __half2 h0 = __floats2half2_rn(v.x, v.y);
            __half2 h1 = __floats2half2_rn(v.z, v.w);
            uint2 wv;
            wv.x = *reinterpret_cast<unsigned*>(&h0);
            wv.y = *reinterpret_cast<unsigned*>(&h1);
            *(uint2*)&g_ref[(size_t)idx * 4] = wv;
        }
        return;
    }

    __shared__ float tile[32][132];
    int pix0 = blockIdx.x * 128;
    int c0 = blockIdx.y * 32;
    const float* __restrict__ src = (z == 0) ? fm : (z == 1) ? gx : gy;
    int off = z * 128 + c0;

    int tx = threadIdx.x, ty = threadIdx.y;
#pragma unroll
    for (int k = 0; k < 4; k++) {
        int ch = ty + 8 * k;
        float4 v = *(const float4*)&src[(size_t)(c0 + ch) * HWIM + pix0 + tx * 4];
        *(float4*)&tile[ch][tx * 4] = v;
    }
    __syncthreads();

    int t = ty * 32 + tx;
#pragma unroll
    for (int i = 0; i < 2; i++) {
        int id = i * 256 + t;       // 0..511
        int pl = id >> 2;           // 0..127
        int cg = (id & 3) * 8;      // 0,8,16,24
        __half2 h0 = __floats2half2_rn(tile[cg + 0][pl], tile[cg + 1][pl]);
        __half2 h1 = __floats2half2_rn(tile[cg + 2][pl], tile[cg + 3][pl]);
        __half2 h2v = __floats2half2_rn(tile[cg + 4][pl], tile[cg + 5][pl]);
        __half2 h3 = __floats2half2_rn(tile[cg + 6][pl], tile[cg + 7][pl]);
        uint4 wv;
        wv.x = *reinterpret_cast<unsigned*>(&h0);
        wv.y = *reinterpret_cast<unsigned*>(&h1);
        wv.z = *reinterpret_cast<unsigned*>(&h2v);
        wv.w = *reinterpret_cast<unsigned*>(&h3);
        *(uint4*)&g_maps[(size_t)(pix0 + pl) * 384 + off + cg] = wv;
    }
}

// 2 points per warp; lane = 16*group + lane16; each lane covers 8 channels
// (8*lane16 .. 8*lane16+7) = ONE uint4 per array -> depth-2 data pipeline fits
// in registers: next iteration's gathers are issued BEFORE consuming the
// current one, hiding the gather latency everywhere except iteration 0.
// Last finishing block runs the LM solve (it<5) or final output (it==5).
template <bool COST_ONLY>
__global__ void __launch_bounds__(256, 3) k_pass(const float* __restrict__ pts,
                                                 const float* __restrict__ Km,
                                                 int N, int it,
                                                 float* __restrict__ out) {
    int lane = threadIdx.x & 31;
    int lane16 = lane & 15;
    int group = lane >> 4;
    int warpId = blockIdx.x * 8 + (threadIdx.x >> 5);
    int nWarps = gridDim.x * 8;

    // Per-lane term (i,j) table: term t = lane16 + 16q, packed ti | tj<<8
    int tij[2];
#pragma unroll
    for (int q = 0; q < 2; q++) {
        int t = lane16 + 16 * q;
        int i = 0, j = 0;
        if (t < 21) {
            int tt = t;
            while (tt >= 6 - i) { tt -= 6 - i; i++; }
            j = i + tt;
        } else if (t < 27) {
            i = t - 21; j = i;
        }
        tij[q] = i | (j << 8);
    }

    float acc[2] = {0.f, 0.f};

    float R0 = g_Rc[0], R1 = g_Rc[1], R2 = g_Rc[2];
    float R3 = g_Rc[3], R4 = g_Rc[4], R5 = g_Rc[5];
    float R6 = g_Rc[6], R7 = g_Rc[7], R8 = g_Rc[8];
    float t0 = g_tc[0], t1 = g_tc[1], t2 = g_tc[2];
    float k00 = Km[0], k01 = Km[1], k02 = Km[2];
    float k10 = Km[3], k11 = Km[4], k12 = Km[5];
    float k20 = Km[6], k21 = Km[7], k22 = Km[8];

    // Project point batch `bs`: outputs mask, row index, pixel, per-lane svalA/svalB.
    auto project = [&](int bs, float& msk, int& ldn, int& pix,
                       float& svalA, float& svalB) {
        int n = bs + group;
        msk = (n < N) ? 1.0f : 0.0f;
        ldn = min(n, N - 1);
        float X = __ldg(pts + 3 * ldn + 0);
        float Y = __ldg(pts + 3 * ldn + 1);
        float Z = __ldg(pts + 3 * ldn + 2);
        float px = fmaf(R0, X, fmaf(R1, Y, fmaf(R2, Z, t0)));
        float py = fmaf(R3, X, fmaf(R4, Y, fmaf(R5, Z, t1)));
        float pz = fmaf(R6, X, fmaf(R7, Y, fmaf(R8, Z, t2)));
        float u = fmaf(k00, px, fmaf(k01, py, k02 * pz));
        float v = fmaf(k10, px, fmaf(k11, py, k12 * pz));
        float w = fmaf(k20, px, fmaf(k21, py, k22 * pz));
        int jj = min(max((int)rintf(u / w) - 1, 0), WIM - 1);
        int ii = min(max((int)rintf(v / w) - 1, 0), HIM - 1);
        pix = ii * WIM + jj;
        if (!COST_ONLY) {
            float fx = k00, fy = k11;
            float iz = 1.0f / pz;
            float xz = px * iz, yz = py * iz;
            float A0 = fx * iz, A1 = 0.f, A2 = -fx * xz * iz;
            float A3 = -fx * xz * yz, A4 = fx * (1.0f + xz * xz), A5 = -fx * yz;
            float B0 = 0.f, B1 = fy * iz, B2 = -fy * yz * iz;
            float B3 = -fy * (1.0f + yz * yz), B4 = fy * xz * yz, B5 = fy * xz;
            svalA = (lane16 == 0) ? A0 : (lane16 == 1) ? A1 : (lane16 == 2) ? A2
                   : (lane16 == 3) ? A3 : (lane16 == 4) ? A4 : A5;
            svalB = (lane16 == 0) ? B0 : (lane16 == 1) ? B1 : (lane16 == 2) ? B2
                   : (lane16 == 3) ? B3 : (lane16 == 4) ? B4 : B5;
        } else {
            svalA = 0.f; svalB = 0.f;
        }
    };

    // Issue gathers for (pix, ldn) into a 4-uint4 buffer.
    auto issue = [&](int pix, int ldn, uint4& f, uint4& r, uint4& a, uint4& b) {
        const uint4* __restrict__ m4 = (const uint4*)(g_maps + (size_t)pix * 384);
        const uint4* __restrict__ r4 = (const uint4*)(g_ref + (size_t)ldn * CCH);
        f = m4[lane16];
        r = r4[lane16];
        if (!COST_ONLY) {
            a = m4[16 + lane16];
            b = m4[32 + lane16];
        }
    };

    // Consume a buffer: channel sums, width-16 butterfly, term accumulation.
    auto consume = [&](const uint4& f, const uint4& r, const uint4& a, const uint4& b,
                       float msk, float svalA, float svalB) {
        float sc = 0.f, sxx = 0.f, sxy = 0.f, syy = 0.f, sxe = 0.f, sye = 0.f;
#define STEP(FU, RU, AU, BU)                                              \
        do {                                                              \
            float2 fv = cvt2(FU), rv = cvt2(RU);                          \
            float ex = fv.x - rv.x, ey = fv.y - rv.y;                     \
            sc = fmaf(ex, ex, fmaf(ey, ey, sc));                          \
            if (!COST_ONLY) {                                             \
                float2 av = cvt2(AU), bv = cvt2(BU);                      \
                sxe = fmaf(av.x, ex, fmaf(av.y, ey, sxe));                \
                sye = fmaf(bv.x, ex, fmaf(bv.y, ey, sye));                \
                sxx = fmaf(av.x, av.x, fmaf(av.y, av.y, sxx));            \
                sxy = fmaf(av.x, bv.x, fmaf(av.y, bv.y, sxy));            \
                syy = fmaf(bv.x, bv.x, fmaf(bv.y, bv.y, syy));            \
            }                                                             \
        } while (0)
        STEP(f.x, r.x, a.x, b.x);
        STEP(f.y, r.y, a.y, b.y);
        STEP(f.z, r.z, a.z, b.z);
        STEP(f.w, r.w, a.w, b.w);
#undef STEP

        sc *= msk;
        if (!COST_ONLY) { sxx *= msk; sxy *= msk; syy *= msk; sxe *= msk; sye *= msk; }

        // Width-16 butterfly (stays within each point's lane group)
#pragma unroll
        for (int d = 1; d < 16; d <<= 1) {
            sc += __shfl_xor_sync(0xffffffffu, sc, d);
            if (!COST_ONLY) {
                sxx += __shfl_xor_sync(0xffffffffu, sxx, d);
                sxy += __shfl_xor_sync(0xffffffffu, sxy, d);
                syy += __shfl_xor_sync(0xffffffffu, syy, d);
                sxe += __shfl_xor_sync(0xffffffffu, sxe, d);
                sye += __shfl_xor_sync(0xffffffffu, sye, d);
            }
        }

        if (!COST_ONLY) {
#pragma unroll
            for (int q = 0; q < 2; q++) {
                int i = tij[q] & 0xff, j = tij[q] >> 8;
                float Ai = __shfl_sync(0xffffffffu, svalA, i, 16);
                float Aj = __shfl_sync(0xffffffffu, svalA, j, 16);
                float Bi = __shfl_sync(0xffffffffu, svalB, i, 16);
                float Bj = __shfl_sync(0xffffffffu, svalB, j, 16);
                float hess = sxx * Ai * Aj + sxy * (Ai * Bj + Aj * Bi) + syy * Bi * Bj;
                float grad = sxe * Ai + sye * Bi;
                int t = lane16 + 16 * q;
                float term = (t < 21) ? hess : (t < 27) ? grad : (t == 27) ? sc : 0.0f;
                acc[q] += term;
            }
        } else {
            if (lane16 == 11) acc[1] += sc;   // t = 11 + 16 = 27
        }
    };

    // Depth-2 software pipeline over 2-point batches
    int stride = nWarps * 2;
    int base = warpId * 2;
    if (base < N) {
        float m0, A0v, B0v, m1, A1v, B1v;
        int l0, p0, l1, p1;
        uint4 f0, r0, a0, b0, f1, r1, a1, b1;

        project(base, m0, l0, p0, A0v, B0v);
        issue(p0, l0, f0, r0, a0, b0);

        for (;;) {
            int nb = base + stride;
            bool nh = (nb < N);
            if (nh) {
                project(nb, m1, l1, p1, A1v, B1v);
                issue(p1, l1, f1, r1, a1, b1);
            }
            consume(f0, r0, a0, b0, m0, A0v, B0v);
            if (!nh) break;

            int nb2 = nb + stride;
            bool nh2 = (nb2 < N);
            if (nh2) {
                project(nb2, m0, l0, p0, A0v, B0v);
                issue(p0, l0, f0, r0, a0, b0);
            }
            consume(f1, r1, a1, b1, m1, A1v, B1v);
            if (!nh2) break;
            base = nb2;
        }
    }

    // Reduce across the 2 groups (xor 16)
#pragma unroll
    for (int q = 0; q < 2; q++) {
        acc[q] += __shfl_xor_sync(0xffffffffu, acc[q], 16);
    }

    __shared__ double sh[28];
    if (threadIdx.x < 28) sh[threadIdx.x] = 0.0;
    __syncthreads();
    if (lane < 16) {
#pragma unroll
        for (int q = 0; q < 2; q++) {
            int t = lane + 16 * q;
            if (t < 28) atomicAdd(&sh[t], (double)acc[q]);
        }
    }
    __syncthreads();
    if (threadIdx.x < 28) atomicAdd(&g_acc[threadIdx.x], sh[threadIdx.x]);

    __threadfence();
    __syncthreads();

    if (threadIdx.x == 0) {
        unsigned old = atomicAdd(&g_counter, 1u);
        if (old == gridDim.x - 1) {
            g_counter = 0;
            if (it < 5) do_solve(it, N);
            else do_final(N, out);
        }
    }
}

extern "C" void kernel_launch(void* const* d_in, const int* in_sizes, int n_in,
                              void* d_out, int out_size) {
    const float* pts = (const float*)d_in[0];
    const float* ref = (const float*)d_in[1];
    const float* fm  = (const float*)d_in[2];
    const float* gx  = (const float*)d_in[3];
    const float* gy  = (const float*)d_in[4];
    const float* Km  = (const float*)d_in[5];
    float* out = (float*)d_out;

    int N = in_sizes[0] / 3;

    dim3 tb(32, 8);
    dim3 tg(HWIM / 128, CCH / 32, 4);   // z=0..2 transpose, z=3 refcvt
    k_transpose<<<tg, tb>>>(fm, gx, gy, ref, N);

    // 3 CTAs/SM (148 SMs * 3 = 444 blocks) — proven best config
    const int passBlocks = 444;
    for (int it = 0; it < 5; it++) {
        k_pass<false><<<passBlocks, 256>>>(pts, Km, N, it, out);
    }
    k_pass<true><<<passBlocks, 256>>>(pts, Km, N, 5, out);
}

// round 16
// speedup vs baseline: 1.1813x; 1.1813x over previous
#include <cuda_runtime.h>
#include <cuda_fp16.h>
#include <math.h>

#define CCH 128
#define HIM 480
#define WIM 640
#define HWIM (HIM * WIM)
#define NMAX 100000

// Fused transposed fp16 maps: per pixel 384 halves: [0:128]=fm, [128:256]=gx, [256:384]=gy
__device__ __align__(16) __half g_maps[(size_t)HWIM * 384];
// fp16 copy of feature_ref [N][128]
__device__ __align__(16) __half g_ref[(size_t)NMAX * CCH];

// Reduction accumulators: [0..20] upper-tri Hessian, [21..26] g, [27] sum(e^2)
__device__ double g_acc[28];
__device__ double g_H[21];
__device__ double g_g[6];
__device__ float g_R[9], g_t[3];    // accepted
__device__ float g_Rc[9], g_tc[3];  // candidate (target of the next pass)
__device__ float g_lam, g_lr;
__device__ double g_prev_cost;
__device__ unsigned g_counter = 0;

__device__ __forceinline__ int triidx(int i, int j) {  // i <= j
    return i * (13 - i) / 2 + (j - i);
}

__device__ __forceinline__ float2 cvt2(unsigned v) {
    __half2 h = *reinterpret_cast<const __half2*>(&v);
    return __half22float2(h);
}

// Swizzled smem column for the transpose tile: pixel-group px4 (0..31) of
// channel ch lives at float4-column (px4 + ch + (ch>>3)) & 31. Eliminates the
// 4-way LDS bank conflicts of the straight layout (proof in commit message).
__device__ __forceinline__ int swcol(int px4, int ch) {
    return (px4 + ch + (ch >> 3)) & 31;
}

// fp32 LM solve, run by ONE thread (last block's tail). Builds next candidate.
__device__ __noinline__ void do_solve(int iter, int N) {
    double cost = 0.5 * g_acc[27] / (double)N;
    bool accept;
    if (iter == 0) {
        g_prev_cost = cost;
        accept = true;
    } else {
        bool worse = (cost > g_prev_cost);
        float lam = g_lam * (worse ? 10.0f : 0.1f);
        g_lam = fminf(fmaxf(lam, 1e-6f), 1e4f);
        if (worse) {
            g_lr = fminf(fmaxf(0.1f * g_lr, 1e-3f), 1.0f);
        } else {
            g_lr = 0.1f;
        }
        accept = !worse;
        if (accept) g_prev_cost = cost;
    }
    if (accept) {
        for (int i = 0; i < 21; i++) g_H[i] = g_acc[i];
        for (int i = 0; i < 6; i++) g_g[i] = g_acc[21 + i];
        for (int i = 0; i < 9; i++) g_R[i] = g_Rc[i];
        for (int i = 0; i < 3; i++) g_t[i] = g_tc[i];
    }

    float M[6][7];
    float lam = g_lam;
    for (int i = 0; i < 6; i++) {
        for (int j = i; j < 6; j++) {
            float h = (float)g_H[triidx(i, j)];
            M[i][j] = h;
            M[j][i] = h;
        }
    }
    for (int i = 0; i < 6; i++) {
        float hd = (float)g_H[triidx(i, i)];
        M[i][i] = hd + (hd + 1e-9f) * lam;
        M[i][6] = (float)g_g[i];
    }

    for (int k = 0; k < 6; k++) {
        int p = k;
        float mx = fabsf(M[k][k]);
        for (int r = k + 1; r < 6; r++) {
            float a = fabsf(M[r][k]);
            if (a > mx) { mx = a; p = r; }
        }
        if (p != k) {
            for (int c = k; c < 7; c++) { float tmp = M[k][c]; M[k][c] = M[p][c]; M[p][c] = tmp; }
        }
        float d = M[k][k];
        for (int r = k + 1; r < 6; r++) {
            float f = M[r][k] / d;
            for (int c = k; c < 7; c++) M[r][c] -= f * M[k][c];
        }
    }
    float x[6];
    for (int i = 5; i >= 0; i--) {
        float s = M[i][6];
        for (int j = i + 1; j < 6; j++) s -= M[i][j] * x[j];
        x[i] = s / M[i][i];
    }

    float lr = g_lr;
    float dt0 = -lr * x[0], dt1 = -lr * x[1], dt2 = -lr * x[2];
    float wx = -lr * x[3], wy = -lr * x[4], wz = -lr * x[5];

    float th = sqrtf(wx * wx + wy * wy + wz * wz);
    float Ac, Bc;
    if (th < 1e-7f) { Ac = 1.0f; Bc = 0.5f; }
    else { Ac = sinf(th) / th; Bc = (1.0f - cosf(th)) / (th * th); }
    float Wm[3][3] = {{0.0f, -wz, wy}, {wz, 0.0f, -wx}, {-wy, wx, 0.0f}};
    float W2[3][3];
    for (int i = 0; i < 3; i++)
        for (int j = 0; j < 3; j++) {
            float s = 0.0f;
            for (int k = 0; k < 3; k++) s += Wm[i][k] * Wm[k][j];
            W2[i][j] = s;
        }
    float dR[3][3];
    for (int i = 0; i < 3; i++)
        for (int j = 0; j < 3; j++)
            dR[i][j] = (i == j ? 1.0f : 0.0f) + Ac * Wm[i][j] + Bc * W2[i][j];

    float Rn[3][3], tn[3];
    for (int i = 0; i < 3; i++) {
        for (int j = 0; j < 3; j++) {
            float s = 0.0f;
            for (int k = 0; k < 3; k++) s += dR[i][k] * g_R[k * 3 + j];
            Rn[i][j] = s;
        }
        float s = 0.0f;
        for (int k = 0; k < 3; k++) s += dR[i][k] * g_t[k];
        tn[i] = s;
    }
    tn[0] += dt0; tn[1] += dt1; tn[2] += dt2;

    for (int i = 0; i < 3; i++)
        for (int j = 0; j < 3; j++)
            g_Rc[i * 3 + j] = Rn[i][j];
    for (int i = 0; i < 3; i++) g_tc[i] = tn[i];

    for (int i = 0; i < 28; i++) g_acc[i] = 0.0;
}

__device__ __noinline__ void do_final(int N, float* __restrict__ out) {
    double cost = 0.5 * g_acc[27] / (double)N;
    bool worse = (cost > g_prev_cost);
    const float* R = worse ? g_R : g_Rc;
    const float* t = worse ? g_t : g_tc;
    for (int i = 0; i < 9; i++) out[i] = R[i];
    for (int i = 0; i < 3; i++) out[9 + i] = t[i];
    for (int i = 0; i < 28; i++) g_acc[i] = 0.0;
}

// Transpose all three (C=128, HW) fp32 maps into fp16 g_maps[pix*384 + z*128 + c].
// z==3 slice instead converts feature_ref fp32 -> fp16 (fused refcvt).
// Block (0,0,0) thread (0,0) also performs global-state init.
// The smem tile uses a swizzled column layout (see swcol) so both the STS.128
// writes and the transposed LDS reads are bank-conflict-free.
__global__ void __launch_bounds__(256) k_transpose(const float* __restrict__ fm,
                                                   const float* __restrict__ gx,
                                                   const float* __restrict__ gy,
                                                   const float* __restrict__ ref,
                                                   int N) {
    if (blockIdx.x == 0 && blockIdx.y == 0 && blockIdx.z == 0 &&
        threadIdx.x == 0 && threadIdx.y == 0) {
        for (int i = 0; i < 9; i++) {
            float v = (i % 4 == 0) ? 1.0f : 0.0f;
            g_R[i] = v; g_Rc[i] = v;
        }
        g_t[0] = 1.0f; g_t[1] = 1.0f; g_t[2] = 0.0f;
        g_tc[0] = 1.0f; g_tc[1] = 1.0f; g_tc[2] = 0.0f;
        g_lam = 0.01f; g_lr = 0.1f;
        g_prev_cost = 0.0;
        for (int i = 0; i < 28; i++) g_acc[i] = 0.0;
        g_counter = 0;
    }

    int z = blockIdx.z;
    if (z == 3) {
        // refcvt: grid-stride over 4-float chunks
        int tid = (blockIdx.y * gridDim.x + blockIdx.x) * 256 + threadIdx.y * 32 + threadIdx.x;
        int nThreads = gridDim.x * gridDim.y * 256;
        int total4 = N * (CCH / 4);
        for (int idx = tid; idx < total4; idx += nThreads) {
            float4 v = *(const float4*)&ref[(size_t)idx * 4];
            __half2 h0 = __floats2half2_rn(v.x, v.y);
            __half2 h1 = __floats2half2_rn(v.z, v.w);
            uint2 wv;
            wv.x = *reinterpret_cast<unsigned*>(&h0);
            wv.y = *reinterpret_cast<unsigned*>(&h1);
            *(uint2*)&g_ref[(size_t)idx * 4] = wv;
        }
        return;
    }

    __shared__ float tile[32][132];
    int pix0 = blockIdx.x * 128;
    int c0 = blockIdx.y * 32;
    const float* __restrict__ src = (z == 0) ? fm : (z == 1) ? gx : gy;
    int off = z * 128 + c0;

    int tx = threadIdx.x, ty = threadIdx.y;
#pragma unroll
    for (int k = 0; k < 4; k++) {
        int ch = ty + 8 * k;
        float4 v = *(const float4*)&src[(size_t)(c0 + ch) * HWIM + pix0 + tx * 4];
        *(float4*)&tile[ch][swcol(tx, ch) * 4] = v;
    }
    __syncthreads();

    int t = ty * 32 + tx;
#pragma unroll
    for (int i = 0; i < 2; i++) {
        int id = i * 256 + t;       // 0..511
        int pl = id >> 2;           // 0..127
        int cg = (id & 3) * 8;      // 0,8,16,24
        int p4 = pl >> 2, pr = pl & 3;
#define TL(J) tile[cg + (J)][swcol(p4, cg + (J)) * 4 + pr]
        __half2 h0 = __floats2half2_rn(TL(0), TL(1));
        __half2 h1 = __floats2half2_rn(TL(2), TL(3));
        __half2 h2v = __floats2half2_rn(TL(4), TL(5));
        __half2 h3 = __floats2half2_rn(TL(6), TL(7));
#undef TL
        uint4 wv;
        wv.x = *reinterpret_cast<unsigned*>(&h0);
        wv.y = *reinterpret_cast<unsigned*>(&h1);
        wv.z = *reinterpret_cast<unsigned*>(&h2v);
        wv.w = *reinterpret_cast<unsigned*>(&h3);
        *(uint4*)&g_maps[(size_t)(pix0 + pl) * 384 + off + cg] = wv;
    }
}

// 4 points per warp; lane = 8*group + lane8; lane covers 16 channels:
// 8*lane8..8*lane8+7 and 64+8*lane8..64+8*lane8+7.
// fp32 STEP math. Next point's projection is computed while current gathers
// are in flight. Last finishing block runs the LM solve (it<5) or final (it==5).
template <bool COST_ONLY>
__global__ void __launch_bounds__(256, 3) k_pass(const float* __restrict__ pts,
                                                 const float* __restrict__ Km,
                                                 int N, int it,
                                                 float* __restrict__ out) {
    int lane = threadIdx.x & 31;
    int lane8 = lane & 7;
    int group = lane >> 3;
    int warpId = blockIdx.x * 8 + (threadIdx.x >> 5);
    int nWarps = gridDim.x * 8;

    // Per-lane term (i,j) table: term t = lane8 + 8q, packed ti | tj<<8
    int tij[4];
#pragma unroll
    for (int q = 0; q < 4; q++) {
        int t = lane8 + 8 * q;
        int i = 0, j = 0;
        if (t < 21) {
            int tt = t;
            while (tt >= 6 - i) { tt -= 6 - i; i++; }
            j = i + tt;
        } else if (t < 27) {
            i = t - 21; j = i;
        }
        tij[q] = i | (j << 8);
    }

    float acc[4] = {0.f, 0.f, 0.f, 0.f};

    float R0 = g_Rc[0], R1 = g_Rc[1], R2 = g_Rc[2];
    float R3 = g_Rc[3], R4 = g_Rc[4], R5 = g_Rc[5];
    float R6 = g_Rc[6], R7 = g_Rc[7], R8 = g_Rc[8];
    float t0 = g_tc[0], t1 = g_tc[1], t2 = g_tc[2];
    float k00 = Km[0], k01 = Km[1], k02 = Km[2];
    float k10 = Km[3], k11 = Km[4], k12 = Km[5];
    float k20 = Km[6], k21 = Km[7], k22 = Km[8];

    // Project point batch `bs`: outputs mask, row index, pixel, per-lane svalA/svalB.
    auto project = [&](int bs, float& msk, int& ldn, int& pix,
                       float& svalA, float& svalB) {
        int n = bs + group;
        msk = (n < N) ? 1.0f : 0.0f;
        ldn = min(n, N - 1);
        float X = __ldg(pts + 3 * ldn + 0);
        float Y = __ldg(pts + 3 * ldn + 1);
        float Z = __ldg(pts + 3 * ldn + 2);
        float px = fmaf(R0, X, fmaf(R1, Y, fmaf(R2, Z, t0)));
        float py = fmaf(R3, X, fmaf(R4, Y, fmaf(R5, Z, t1)));
        float pz = fmaf(R6, X, fmaf(R7, Y, fmaf(R8, Z, t2)));
        float u = fmaf(k00, px, fmaf(k01, py, k02 * pz));
        float v = fmaf(k10, px, fmaf(k11, py, k12 * pz));
        float w = fmaf(k20, px, fmaf(k21, py, k22 * pz));
        int jj = min(max((int)rintf(u / w) - 1, 0), WIM - 1);
        int ii = min(max((int)rintf(v / w) - 1, 0), HIM - 1);
        pix = ii * WIM + jj;
        if (!COST_ONLY) {
            float fx = k00, fy = k11;
            float iz = 1.0f / pz;
            float xz = px * iz, yz = py * iz;
            float A0 = fx * iz, A1 = 0.f, A2 = -fx * xz * iz;
            float A3 = -fx * xz * yz, A4 = fx * (1.0f + xz * xz), A5 = -fx * yz;
            float B0 = 0.f, B1 = fy * iz, B2 = -fy * yz * iz;
            float B3 = -fy * (1.0f + yz * yz), B4 = fy * xz * yz, B5 = fy * xz;
            svalA = (lane8 == 0) ? A0 : (lane8 == 1) ? A1 : (lane8 == 2) ? A2
                   : (lane8 == 3) ? A3 : (lane8 == 4) ? A4 : A5;
            svalB = (lane8 == 0) ? B0 : (lane8 == 1) ? B1 : (lane8 == 2) ? B2
                   : (lane8 == 3) ? B3 : (lane8 == 4) ? B4 : B5;
        } else {
            svalA = 0.f; svalB = 0.f;
        }
    };

    int stride = nWarps * 4;
    int base = warpId * 4;
    bool have = (base < N);
    float cmask, csA, csB;
    int cldn, cpix;
    if (have) project(base, cmask, cldn, cpix, csA, csB);

    while (have) {
        // Issue current gathers (front-batched)
        const uint4* __restrict__ m4 = (const uint4*)(g_maps + (size_t)cpix * 384);
        const uint4* __restrict__ r4 = (const uint4*)(g_ref + (size_t)cldn * CCH);
        uint4 fA = m4[lane8], fB = m4[8 + lane8];
        uint4 rA = r4[lane8], rB = r4[8 + lane8];
        uint4 aA, aB, bA, bB;
        if (!COST_ONLY) {
            aA = m4[16 + lane8]; aB = m4[24 + lane8];
            bA = m4[32 + lane8]; bB = m4[40 + lane8];
        }

        // Overlap: project the NEXT point batch while gathers are in flight
        int nbase = base + stride;
        bool nhave = (nbase < N);
        float nmask = 0.f, nsA = 0.f, nsB = 0.f;
        int nldn = 0, npix = 0;
        if (nhave) project(nbase, nmask, nldn, npix, nsA, nsB);

        // Consume current gathers
        float sc = 0.f, sxx = 0.f, sxy = 0.f, syy = 0.f, sxe = 0.f, sye = 0.f;
#define STEP(FU, RU, AU, BU)                                              \
        do {                                                              \
            float2 fv = cvt2(FU), rv = cvt2(RU);                          \
            float ex = fv.x - rv.x, ey = fv.y - rv.y;                     \
            sc = fmaf(ex, ex, fmaf(ey, ey, sc));                          \
            if (!COST_ONLY) {                                             \
                float2 av = cvt2(AU), bv = cvt2(BU);                      \
                sxe = fmaf(av.x, ex, fmaf(av.y, ey, sxe));                \
                sye = fmaf(bv.x, ex, fmaf(bv.y, ey, sye));                \
                sxx = fmaf(av.x, av.x, fmaf(av.y, av.y, sxx));            \
                sxy = fmaf(av.x, bv.x, fmaf(av.y, bv.y, sxy));            \
                syy = fmaf(bv.x, bv.x, fmaf(bv.y, bv.y, syy));            \
            }                                                             \
        } while (0)
        STEP(fA.x, rA.x, aA.x, bA.x);
        STEP(fA.y, rA.y, aA.y, bA.y);
        STEP(fA.z, rA.z, aA.z, bA.z);
        STEP(fA.w, rA.w, aA.w, bA.w);
        STEP(fB.x, rB.x, aB.x, bB.x);
        STEP(fB.y, rB.y, aB.y, bB.y);
        STEP(fB.z, rB.z, aB.z, bB.z);
        STEP(fB.w, rB.w, aB.w, bB.w);
#undef STEP

        sc *= cmask;
        if (!COST_ONLY) { sxx *= cmask; sxy *= cmask; syy *= cmask; sxe *= cmask; sye *= cmask; }

        // Width-8 butterfly (stays within each point's lane group)
#pragma unroll
        for (int d = 1; d < 8; d <<= 1) {
            sc += __shfl_xor_sync(0xffffffffu, sc, d);
            if (!COST_ONLY) {
                sxx += __shfl_xor_sync(0xffffffffu, sxx, d);
                sxy += __shfl_xor_sync(0xffffffffu, sxy, d);
                syy += __shfl_xor_sync(0xffffffffu, syy, d);
                sxe += __shfl_xor_sync(0xffffffffu, sxe, d);
                sye += __shfl_xor_sync(0xffffffffu, sye, d);
            }
        }

        if (!COST_ONLY) {
#pragma unroll
            for (int q = 0; q < 4; q++) {
                int i = tij[q] & 0xff, j = tij[q] >> 8;
                float Ai = __shfl_sync(0xffffffffu, csA, i, 8);
                float Aj = __shfl_sync(0xffffffffu, csA, j, 8);
                float Bi = __shfl_sync(0xffffffffu, csB, i, 8);
                float Bj = __shfl_sync(0xffffffffu, csB, j, 8);
                float hess = sxx * Ai * Aj + sxy * (Ai * Bj + Aj * Bi) + syy * Bi * Bj;
                float grad = sxe * Ai + sye * Bi;
                int t = lane8 + 8 * q;
                float term = (t < 21) ? hess : (t < 27) ? grad : (t == 27) ? sc : 0.0f;
                acc[q] += term;
            }
        } else {
            if (lane8 == 3) acc[3] += sc;   // t = 27
        }

        base = nbase; have = nhave;
        cmask = nmask; cldn = nldn; cpix = npix; csA = nsA; csB = nsB;
    }

    // Reduce across the 4 groups (xor 8, 16)
#pragma unroll
    for (int q = 0; q < 4; q++) {
        acc[q] += __shfl_xor_sync(0xffffffffu, acc[q], 8);
        acc[q] += __shfl_xor_sync(0xffffffffu, acc[q], 16);
    }

    __shared__ double sh[28];
    if (threadIdx.x < 28) sh[threadIdx.x] = 0.0;
    __syncthreads();
    if (lane < 8) {
#pragma unroll
        for (int q = 0; q < 4; q++) {
            int t = lane + 8 * q;
            if (t < 28) atomicAdd(&sh[t], (double)acc[q]);
        }
    }
    __syncthreads();
    if (threadIdx.x < 28) atomicAdd(&g_acc[threadIdx.x], sh[threadIdx.x]);

    __threadfence();
    __syncthreads();

    if (threadIdx.x == 0) {
        unsigned old = atomicAdd(&g_counter, 1u);
        if (old == gridDim.x - 1) {
            g_counter = 0;
            if (it < 5) do_solve(it, N);
            else do_final(N, out);
        }
    }
}

extern "C" void kernel_launch(void* const* d_in, const int* in_sizes, int n_in,
                              void* d_out, int out_size) {
    const float* pts = (const float*)d_in[0];
    const float* ref = (const float*)d_in[1];
    const float* fm  = (const float*)d_in[2];
    const float* gx  = (const float*)d_in[3];
    const float* gy  = (const float*)d_in[4];
    const float* Km  = (const float*)d_in[5];
    float* out = (float*)d_out;

    int N = in_sizes[0] / 3;

    dim3 tb(32, 8);
    dim3 tg(HWIM / 128, CCH / 32, 4);   // z=0..2 transpose, z=3 refcvt
    k_transpose<<<tg, tb>>>(fm, gx, gy, ref, N);

    // 3 CTAs/SM (148 SMs * 3 = 444 blocks) — proven best config
    const int passBlocks = 444;
    for (int it = 0; it < 5; it++) {
        k_pass<false><<<passBlocks, 256>>>(pts, Km, N, it, out);
    }
    k_pass<true><<<passBlocks, 256>>>(pts, Km, N, 5, out);
}

// round 17
// speedup vs baseline: 1.1876x; 1.0053x over previous
#include <cuda_runtime.h>
#include <cuda_fp16.h>
#include <math.h>

#define CCH 128
#define HIM 480
#define WIM 640
#define HWIM (HIM * WIM)
#define NMAX 100000

// Fused transposed fp16 maps: per pixel 384 halves: [0:128]=fm, [128:256]=gx, [256:384]=gy
__device__ __align__(16) __half g_maps[(size_t)HWIM * 384];
// fp16 copy of feature_ref [N][128]
__device__ __align__(16) __half g_ref[(size_t)NMAX * CCH];

// Reduction accumulators: [0..20] upper-tri Hessian, [21..26] g, [27] sum(e^2)
__device__ double g_acc[28];
__device__ double g_H[21];
__device__ double g_g[6];
__device__ float g_R[9], g_t[3];    // accepted
__device__ float g_Rc[9], g_tc[3];  // candidate (target of the next pass)
__device__ float g_lam, g_lr;
__device__ double g_prev_cost;
__device__ unsigned g_counter = 0;

__device__ __forceinline__ int triidx(int i, int j) {  // i <= j
    return i * (13 - i) / 2 + (j - i);
}

__device__ __forceinline__ float2 cvt2(unsigned v) {
    __half2 h = *reinterpret_cast<const __half2*>(&v);
    return __half22float2(h);
}

// Swizzled smem column for the transpose tile: pixel-group px4 (0..31) of
// channel ch lives at float4-column (px4 + ch + (ch>>3)) & 31. Eliminates the
// 4-way LDS bank conflicts of the straight layout.
__device__ __forceinline__ int swcol(int px4, int ch) {
    return (px4 + ch + (ch >> 3)) & 31;
}

// fp32 LM solve, run by ONE thread (last block's tail). Builds next candidate.
__device__ __noinline__ void do_solve(int iter, int N) {
    double cost = 0.5 * g_acc[27] / (double)N;
    bool accept;
    if (iter == 0) {
        g_prev_cost = cost;
        accept = true;
    } else {
        bool worse = (cost > g_prev_cost);
        float lam = g_lam * (worse ? 10.0f : 0.1f);
        g_lam = fminf(fmaxf(lam, 1e-6f), 1e4f);
        if (worse) {
            g_lr = fminf(fmaxf(0.1f * g_lr, 1e-3f), 1.0f);
        } else {
            g_lr = 0.1f;
        }
        accept = !worse;
        if (accept) g_prev_cost = cost;
    }
    if (accept) {
        for (int i = 0; i < 21; i++) g_H[i] = g_acc[i];
        for (int i = 0; i < 6; i++) g_g[i] = g_acc[21 + i];
        for (int i = 0; i < 9; i++) g_R[i] = g_Rc[i];
        for (int i = 0; i < 3; i++) g_t[i] = g_tc[i];
    }

    float M[6][7];
    float lam = g_lam;
    for (int i = 0; i < 6; i++) {
        for (int j = i; j < 6; j++) {
            float h = (float)g_H[triidx(i, j)];
            M[i][j] = h;
            M[j][i] = h;
        }
    }
    for (int i = 0; i < 6; i++) {
        float hd = (float)g_H[triidx(i, i)];
        M[i][i] = hd + (hd + 1e-9f) * lam;
        M[i][6] = (float)g_g[i];
    }

    for (int k = 0; k < 6; k++) {
        int p = k;
        float mx = fabsf(M[k][k]);
        for (int r = k + 1; r < 6; r++) {
            float a = fabsf(M[r][k]);
            if (a > mx) { mx = a; p = r; }
        }
        if (p != k) {
            for (int c = k; c < 7; c++) { float tmp = M[k][c]; M[k][c] = M[p][c]; M[p][c] = tmp; }
        }
        float d = M[k][k];
        for (int r = k + 1; r < 6; r++) {
            float f = M[r][k] / d;
            for (int c = k; c < 7; c++) M[r][c] -= f * M[k][c];
        }
    }
    float x[6];
    for (int i = 5; i >= 0; i--) {
        float s = M[i][6];
        for (int j = i + 1; j < 6; j++) s -= M[i][j] * x[j];
        x[i] = s / M[i][i];
    }

    float lr = g_lr;
    float dt0 = -lr * x[0], dt1 = -lr * x[1], dt2 = -lr * x[2];
    float wx = -lr * x[3], wy = -lr * x[4], wz = -lr * x[5];

    float th = sqrtf(wx * wx + wy * wy + wz * wz);
    float Ac, Bc;
    if (th < 1e-7f) { Ac = 1.0f; Bc = 0.5f; }
    else { Ac = sinf(th) / th; Bc = (1.0f - cosf(th)) / (th * th); }
    float Wm[3][3] = {{0.0f, -wz, wy}, {wz, 0.0f, -wx}, {-wy, wx, 0.0f}};
    float W2[3][3];
    for (int i = 0; i < 3; i++)
        for (int j = 0; j < 3; j++) {
            float s = 0.0f;
            for (int k = 0; k < 3; k++) s += Wm[i][k] * Wm[k][j];
            W2[i][j] = s;
        }
    float dR[3][3];
    for (int i = 0; i < 3; i++)
        for (int j = 0; j < 3; j++)
            dR[i][j] = (i == j ? 1.0f : 0.0f) + Ac * Wm[i][j] + Bc * W2[i][j];

    float Rn[3][3], tn[3];
    for (int i = 0; i < 3; i++) {
        for (int j = 0; j < 3; j++) {
            float s = 0.0f;
            for (int k = 0; k < 3; k++) s += dR[i][k] * g_R[k * 3 + j];
            Rn[i][j] = s;
        }
        float s = 0.0f;
        for (int k = 0; k < 3; k++) s += dR[i][k] * g_t[k];
        tn[i] = s;
    }
    tn[0] += dt0; tn[1] += dt1; tn[2] += dt2;

    for (int i = 0; i < 3; i++)
        for (int j = 0; j < 3; j++)
            g_Rc[i * 3 + j] = Rn[i][j];
    for (int i = 0; i < 3; i++) g_tc[i] = tn[i];

    for (int i = 0; i < 28; i++) g_acc[i] = 0.0;
}

__device__ __noinline__ void do_final(int N, float* __restrict__ out) {
    double cost = 0.5 * g_acc[27] / (double)N;
    bool worse = (cost > g_prev_cost);
    const float* R = worse ? g_R : g_Rc;
    const float* t = worse ? g_t : g_tc;
    for (int i = 0; i < 9; i++) out[i] = R[i];
    for (int i = 0; i < 3; i++) out[9 + i] = t[i];
    for (int i = 0; i < 28; i++) g_acc[i] = 0.0;
}

// Transpose all three (C=128, HW) fp32 maps into fp16 g_maps[pix*384 + z*128 + c].
// z==3 slice instead converts feature_ref fp32 -> fp16 (fused refcvt).
// Block (0,0,0) thread (0,0) also performs global-state init.
// Smem tile uses the swizzled column layout (swcol): STS.128 and transposed
// LDS are both bank-conflict-free.
__global__ void __launch_bounds__(256) k_transpose(const float* __restrict__ fm,
                                                   const float* __restrict__ gx,
                                                   const float* __restrict__ gy,
                                                   const float* __restrict__ ref,
                                                   int N) {
    if (blockIdx.x == 0 && blockIdx.y == 0 && blockIdx.z == 0 &&
        threadIdx.x == 0 && threadIdx.y == 0) {
        for (int i = 0; i < 9; i++) {
            float v = (i % 4 == 0) ? 1.0f : 0.0f;
            g_R[i] = v; g_Rc[i] = v;
        }
        g_t[0] = 1.0f; g_t[1] = 1.0f; g_t[2] = 0.0f;
        g_tc[0] = 1.0f; g_tc[1] = 1.0f; g_tc[2] = 0.0f;
        g_lam = 0.01f; g_lr = 0.1f;
        g_prev_cost = 0.0;
        for (int i = 0; i < 28; i++) g_acc[i] = 0.0;
        g_counter = 0;
    }

    int z = blockIdx.z;
    if (z == 3) {
        // refcvt: grid-stride over 4-float chunks
        int tid = (blockIdx.y * gridDim.x + blockIdx.x) * 256 + threadIdx.y * 32 + threadIdx.x;
        int nThreads = gridDim.x * gridDim.y * 256;
        int total4 = N * (CCH / 4);
        for (int idx = tid; idx < total4; idx += nThreads) {
            float4 v = *(const float4*)&ref[(size_t)idx * 4];
            __half2 h0 = __floats2half2_rn(v.x, v.y);
            __half2 h1 = __floats2half2_rn(v.z, v.w);
            uint2 wv;
            wv.x = *reinterpret_cast<unsigned*>(&h0);
            wv.y = *reinterpret_cast<unsigned*>(&h1);
            *(uint2*)&g_ref[(size_t)idx * 4] = wv;
        }
        return;
    }

    __shared__ float tile[32][132];
    int pix0 = blockIdx.x * 128;
    int c0 = blockIdx.y * 32;
    const float* __restrict__ src = (z == 0) ? fm : (z == 1) ? gx : gy;
    int off = z * 128 + c0;

    int tx = threadIdx.x, ty = threadIdx.y;
#pragma unroll
    for (int k = 0; k < 4; k++) {
        int ch = ty + 8 * k;
        float4 v = *(const float4*)&src[(size_t)(c0 + ch) * HWIM + pix0 + tx * 4];
        *(float4*)&tile[ch][swcol(tx, ch) * 4] = v;
    }
    __syncthreads();

    int t = ty * 32 + tx;
#pragma unroll
    for (int i = 0; i < 2; i++) {
        int id = i * 256 + t;       // 0..511
        int pl = id >> 2;           // 0..127
        int cg = (id & 3) * 8;      // 0,8,16,24
        int p4 = pl >> 2, pr = pl & 3;
#define TL(J) tile[cg + (J)][swcol(p4, cg + (J)) * 4 + pr]
        __half2 h0 = __floats2half2_rn(TL(0), TL(1));
        __half2 h1 = __floats2half2_rn(TL(2), TL(3));
        __half2 h2v = __floats2half2_rn(TL(4), TL(5));
        __half2 h3 = __floats2half2_rn(TL(6), TL(7));
#undef TL
        uint4 wv;
        wv.x = *reinterpret_cast<unsigned*>(&h0);
        wv.y = *reinterpret_cast<unsigned*>(&h1);
        wv.z = *reinterpret_cast<unsigned*>(&h2v);
        wv.w = *reinterpret_cast<unsigned*>(&h3);
        *(uint4*)&g_maps[(size_t)(pix0 + pl) * 384 + off + cg] = wv;
    }
}

// 4 points per warp; lane = 8*group + lane8; lane covers 16 channels:
// 8*lane8..8*lane8+7 and 64+8*lane8..64+8*lane8+7.
// fp32 STEP math. Next point's projection is computed while current gathers
// are in flight. The cost sum (term 27) is accumulated PER-LANE and reduced
// once at the end (no per-iteration butterfly for it); the cost-only pass is
// therefore shuffle-free in its hot loop.
// Last finishing block runs the LM solve (it<5) or final output (it==5).
template <bool COST_ONLY>
__global__ void __launch_bounds__(256, 3) k_pass(const float* __restrict__ pts,
                                                 const float* __restrict__ Km,
                                                 int N, int it,
                                                 float* __restrict__ out) {
    int lane = threadIdx.x & 31;
    int lane8 = lane & 7;
    int group = lane >> 3;
    int warpId = blockIdx.x * 8 + (threadIdx.x >> 5);
    int nWarps = gridDim.x * 8;

    // Per-lane term (i,j) table: term t = lane8 + 8q, packed ti | tj<<8
    int tij[4];
#pragma unroll
    for (int q = 0; q < 4; q++) {
        int t = lane8 + 8 * q;
        int i = 0, j = 0;
        if (t < 21) {
            int tt = t;
            while (tt >= 6 - i) { tt -= 6 - i; i++; }
            j = i + tt;
        } else if (t < 27) {
            i = t - 21; j = i;
        }
        tij[q] = i | (j << 8);
    }

    float acc[4] = {0.f, 0.f, 0.f, 0.f};
    float accSC = 0.f;   // per-lane cost partial (term 27), reduced at the end

    float R0 = g_Rc[0], R1 = g_Rc[1], R2 = g_Rc[2];
    float R3 = g_Rc[3], R4 = g_Rc[4], R5 = g_Rc[5];
    float R6 = g_Rc[6], R7 = g_Rc[7], R8 = g_Rc[8];
    float t0 = g_tc[0], t1 = g_tc[1], t2 = g_tc[2];
    float k00 = Km[0], k01 = Km[1], k02 = Km[2];
    float k10 = Km[3], k11 = Km[4], k12 = Km[5];
    float k20 = Km[6], k21 = Km[7], k22 = Km[8];

    // Project point batch `bs`: outputs mask, row index, pixel, per-lane svalA/svalB.
    auto project = [&](int bs, float& msk, int& ldn, int& pix,
                       float& svalA, float& svalB) {
        int n = bs + group;
        msk = (n < N) ? 1.0f : 0.0f;
        ldn = min(n, N - 1);
        float X = __ldg(pts + 3 * ldn + 0);
        float Y = __ldg(pts + 3 * ldn + 1);
        float Z = __ldg(pts + 3 * ldn + 2);
        float px = fmaf(R0, X, fmaf(R1, Y, fmaf(R2, Z, t0)));
        float py = fmaf(R3, X, fmaf(R4, Y, fmaf(R5, Z, t1)));
        float pz = fmaf(R6, X, fmaf(R7, Y, fmaf(R8, Z, t2)));
        float u = fmaf(k00, px, fmaf(k01, py, k02 * pz));
        float v = fmaf(k10, px, fmaf(k11, py, k12 * pz));
        float w = fmaf(k20, px, fmaf(k21, py, k22 * pz));
        int jj = min(max((int)rintf(u / w) - 1, 0), WIM - 1);
        int ii = min(max((int)rintf(v / w) - 1, 0), HIM - 1);
        pix = ii * WIM + jj;
        if (!COST_ONLY) {
            float fx = k00, fy = k11;
            float iz = 1.0f / pz;
            float xz = px * iz, yz = py * iz;
            float A0 = fx * iz, A1 = 0.f, A2 = -fx * xz * iz;
            float A3 = -fx * xz * yz, A4 = fx * (1.0f + xz * xz), A5 = -fx * yz;
            float B0 = 0.f, B1 = fy * iz, B2 = -fy * yz * iz;
            float B3 = -fy * (1.0f + yz * yz), B4 = fy * xz * yz, B5 = fy * xz;
            svalA = (lane8 == 0) ? A0 : (lane8 == 1) ? A1 : (lane8 == 2) ? A2
                   : (lane8 == 3) ? A3 : (lane8 == 4) ? A4 : A5;
            svalB = (lane8 == 0) ? B0 : (lane8 == 1) ? B1 : (lane8 == 2) ? B2
                   : (lane8 == 3) ? B3 : (lane8 == 4) ? B4 : B5;
        } else {
            svalA = 0.f; svalB = 0.f;
        }
    };

    int stride = nWarps * 4;
    int base = warpId * 4;
    bool have = (base < N);
    float cmask, csA, csB;
    int cldn, cpix;
    if (have) project(base, cmask, cldn, cpix, csA, csB);

    while (have) {
        // Issue current gathers (front-batched)
        const uint4* __restrict__ m4 = (const uint4*)(g_maps + (size_t)cpix * 384);
        const uint4* __restrict__ r4 = (const uint4*)(g_ref + (size_t)cldn * CCH);
        uint4 fA = m4[lane8], fB = m4[8 + lane8];
        uint4 rA = r4[lane8], rB = r4[8 + lane8];
        uint4 aA, aB, bA, bB;
        if (!COST_ONLY) {
            aA = m4[16 + lane8]; aB = m4[24 + lane8];
            bA = m4[32 + lane8]; bB = m4[40 + lane8];
        }

        // Overlap: project the NEXT point batch while gathers are in flight
        int nbase = base + stride;
        bool nhave = (nbase < N);
        float nmask = 0.f, nsA = 0.f, nsB = 0.f;
        int nldn = 0, npix = 0;
        if (nhave) project(nbase, nmask, nldn, npix, nsA, nsB);

        // Consume current gathers
        float sc = 0.f, sxx = 0.f, sxy = 0.f, syy = 0.f, sxe = 0.f, sye = 0.f;
#define STEP(FU, RU, AU, BU)                                              \
        do {                                                              \
            float2 fv = cvt2(FU), rv = cvt2(RU);                          \
            float ex = fv.x - rv.x, ey = fv.y - rv.y;                     \
            sc = fmaf(ex, ex, fmaf(ey, ey, sc));                          \
            if (!COST_ONLY) {                                             \
                float2 av = cvt2(AU), bv = cvt2(BU);                      \
                sxe = fmaf(av.x, ex, fmaf(av.y, ey, sxe));                \
                sye = fmaf(bv.x, ex, fmaf(bv.y, ey, sye));                \
                sxx = fmaf(av.x, av.x, fmaf(av.y, av.y, sxx));            \
                sxy = fmaf(av.x, bv.x, fmaf(av.y, bv.y, sxy));            \
                syy = fmaf(bv.x, bv.x, fmaf(bv.y, bv.y, syy));            \
            }                                                             \
        } while (0)
        STEP(fA.x, rA.x, aA.x, bA.x);
        STEP(fA.y, rA.y, aA.y, bA.y);
        STEP(fA.z, rA.z, aA.z, bA.z);
        STEP(fA.w, rA.w, aA.w, bA.w);
        STEP(fB.x, rB.x, aB.x, bB.x);
        STEP(fB.y, rB.y, aB.y, bB.y);
        STEP(fB.z, rB.z, aB.z, bB.z);
        STEP(fB.w, rB.w, aB.w, bB.w);
#undef STEP

        // Deferred cost reduction: per-lane accumulate; reduce once at the end.
        accSC = fmaf(sc, cmask, accSC);

        if (!COST_ONLY) {
            sxx *= cmask; sxy *= cmask; syy *= cmask; sxe *= cmask; sye *= cmask;

            // Width-8 butterfly (stays within each point's lane group)
#pragma unroll
            for (int d = 1; d < 8; d <<= 1) {
                sxx += __shfl_xor_sync(0xffffffffu, sxx, d);
                sxy += __shfl_xor_sync(0xffffffffu, sxy, d);
                syy += __shfl_xor_sync(0xffffffffu, syy, d);
                sxe += __shfl_xor_sync(0xffffffffu, sxe, d);
                sye += __shfl_xor_sync(0xffffffffu, sye, d);
            }

#pragma unroll
            for (int q = 0; q < 4; q++) {
                int i = tij[q] & 0xff, j = tij[q] >> 8;
                float Ai = __shfl_sync(0xffffffffu, csA, i, 8);
                float Aj = __shfl_sync(0xffffffffu, csA, j, 8);
                float Bi = __shfl_sync(0xffffffffu, csB, i, 8);
                float Bj = __shfl_sync(0xffffffffu, csB, j, 8);
                float hess = sxx * Ai * Aj + sxy * (Ai * Bj + Aj * Bi) + syy * Bi * Bj;
                float grad = sxe * Ai + sye * Bi;
                int t = lane8 + 8 * q;
                float term = (t < 21) ? hess : (t < 27) ? grad : 0.0f;
                acc[q] += term;
            }
        }

        base = nbase; have = nhave;
        cmask = nmask; cldn = nldn; cpix = npix; csA = nsA; csB = nsB;
    }

    // Reduce Hessian/gradient terms across the 4 groups (xor 8, 16)
#pragma unroll
    for (int q = 0; q < 4; q++) {
        acc[q] += __shfl_xor_sync(0xffffffffu, acc[q], 8);
        acc[q] += __shfl_xor_sync(0xffffffffu, acc[q], 16);
    }
    // Full-warp reduce of the cost partial (once per warp)
#pragma unroll
    for (int d = 16; d > 0; d >>= 1)
        accSC += __shfl_xor_sync(0xffffffffu, accSC, d);

    __shared__ double sh[28];
    if (threadIdx.x < 28) sh[threadIdx.x] = 0.0;
    __syncthreads();
    if (lane < 8) {
#pragma unroll
        for (int q = 0; q < 4; q++) {
            int t = lane + 8 * q;
            if (t < 27) atomicAdd(&sh[t], (double)acc[q]);
        }
    }
    if (lane == 0) atomicAdd(&sh[27], (double)accSC);
    __syncthreads();
    if (threadIdx.x < 28) atomicAdd(&g_acc[threadIdx.x], sh[threadIdx.x]);

    __threadfence();
    __syncthreads();

    if (threadIdx.x == 0) {
        unsigned old = atomicAdd(&g_counter, 1u);
        if (old == gridDim.x - 1) {
            g_counter = 0;
            if (it < 5) do_solve(it, N);
            else do_final(N, out);
        }
    }
}

extern "C" void kernel_launch(void* const* d_in, const int* in_sizes, int n_in,
                              void* d_out, int out_size) {
    const float* pts = (const float*)d_in[0];
    const float* ref = (const float*)d_in[1];
    const float* fm  = (const float*)d_in[2];
    const float* gx  = (const float*)d_in[3];
    const float* gy  = (const float*)d_in[4];
    const float* Km  = (const float*)d_in[5];
    float* out = (float*)d_out;

    int N = in_sizes[0] / 3;

    dim3 tb(32, 8);
    dim3 tg(HWIM / 128, CCH / 32, 4);   // z=0..2 transpose, z=3 refcvt
    k_transpose<<<tg, tb>>>(fm, gx, gy, ref, N);

    // 3 CTAs/SM (148 SMs * 3 = 444 blocks) — proven best config
    const int passBlocks = 444;
    for (int it = 0; it < 5; it++) {
        k_pass<false><<<passBlocks, 256>>>(pts, Km, N, it, out);
    }
    k_pass<true><<<passBlocks, 256>>>(pts, Km, N, 5, out);
}